// round 13
// baseline (speedup 1.0000x reference)
#include <cuda_runtime.h>
#include <cuda_fp16.h>
#include <math_constants.h>
#include <cstdint>

// Problem constants
#define BB 2
#define SS 2048
#define EE 1024
#define HH 16
#define DD 64

// Scratch (device globals — allocation-free rule)
__device__ __half g_q [BB * SS * EE];
__device__ __half g_k [BB * SS * EE];
__device__ __half g_v [BB * SS * EE];
__device__ __half g_ctx[BB * SS * EE];
__device__ __half g_xt[BB * SS * EE];        // x in fp16
__device__ __half g_wq[EE * EE];             // W^T in fp16: [N][K]
__device__ __half g_wk[EE * EE];
__device__ __half g_wv[EE * EE];
__device__ __half g_wo[EE * EE];

// Q pre-scale: (1/sqrt(64)) * log2(e)  -> scores in log2 units
#define QSCALE 0.1803368801111204f

// ---------------------------------------------------------------------------
// helpers
// ---------------------------------------------------------------------------
__device__ __forceinline__ void mma16(
    float* c, const uint32_t* a, uint32_t b0, uint32_t b1)
{
    asm volatile(
        "mma.sync.aligned.m16n8k16.row.col.f32.f16.f16.f32 "
        "{%0,%1,%2,%3},{%4,%5,%6,%7},{%8,%9},{%0,%1,%2,%3};\n"
        : "+f"(c[0]), "+f"(c[1]), "+f"(c[2]), "+f"(c[3])
        : "r"(a[0]), "r"(a[1]), "r"(a[2]), "r"(a[3]), "r"(b0), "r"(b1));
}

__device__ __forceinline__ void ldsm4(
    uint32_t& r0, uint32_t& r1, uint32_t& r2, uint32_t& r3, uint32_t addr)
{
    asm volatile(
        "ldmatrix.sync.aligned.m8n8.x4.shared.b16 {%0,%1,%2,%3}, [%4];"
        : "=r"(r0), "=r"(r1), "=r"(r2), "=r"(r3) : "r"(addr));
}

__device__ __forceinline__ void ldsm4t(
    uint32_t& r0, uint32_t& r1, uint32_t& r2, uint32_t& r3, uint32_t addr)
{
    asm volatile(
        "ldmatrix.sync.aligned.m8n8.x4.trans.shared.b16 {%0,%1,%2,%3}, [%4];"
        : "=r"(r0), "=r"(r1), "=r"(r2), "=r"(r3) : "r"(addr));
}

__device__ __forceinline__ float ex2f(float x) {
    float r;
    asm("ex2.approx.f32 %0, %1;" : "=f"(r) : "f"(x));
    return r;
}

__device__ __forceinline__ uint32_t ex2_h2(float a, float b) {
    __half2 h = __floats2half2_rn(a, b);
    uint32_t r;
    asm("ex2.approx.f16x2 %0, %1;" : "=r"(r) : "r"(*(uint32_t*)&h));
    return r;
}

__device__ __forceinline__ void cp16(uint32_t smem_dst, const void* gsrc) {
    asm volatile("cp.async.cg.shared.global [%0], [%1], 16;\n"
                 :: "r"(smem_dst), "l"(gsrc));
}
__device__ __forceinline__ void cp_commit() {
    asm volatile("cp.async.commit_group;\n");
}
template<int N>
__device__ __forceinline__ void cp_wait() {
    asm volatile("cp.async.wait_group %0;\n" :: "n"(N));
}

// ---------------------------------------------------------------------------
// prologue conversions
// ---------------------------------------------------------------------------
__global__ __launch_bounds__(256) void cvt_h(
    const float* __restrict__ src, __half* __restrict__ dst, int n4)
{
    int i = blockIdx.x * blockDim.x + threadIdx.x;
    if (i < n4) {
        float4 v = ((const float4*)src)[i];
        __half2 h0 = __floats2half2_rn(v.x, v.y);
        __half2 h1 = __floats2half2_rn(v.z, v.w);
        *(uint2*)&dst[4 * i] = make_uint2(*(uint32_t*)&h0, *(uint32_t*)&h1);
    }
}

__global__ __launch_bounds__(256) void transcvt_w4(
    const float* __restrict__ W0, const float* __restrict__ W1,
    const float* __restrict__ W2, const float* __restrict__ W3,
    __half* __restrict__ T0, __half* __restrict__ T1,
    __half* __restrict__ T2, __half* __restrict__ T3)
{
    const int z = blockIdx.z;
    const float* W = (z == 0) ? W0 : (z == 1) ? W1 : (z == 2) ? W2 : W3;
    __half* Wt     = (z == 0) ? T0 : (z == 1) ? T1 : (z == 2) ? T2 : T3;

    __shared__ float t[32][33];
    const int n0 = blockIdx.x * 32;
    const int k0 = blockIdx.y * 32;
    const int tx = threadIdx.x;
    const int ty = threadIdx.y;
    #pragma unroll
    for (int i = 0; i < 32; i += 8)
        t[ty + i][tx] = W[(size_t)(k0 + ty + i) * EE + n0 + tx];
    __syncthreads();
    #pragma unroll
    for (int i = 0; i < 32; i += 8)
        Wt[(size_t)(n0 + ty + i) * EE + k0 + tx] = __float2half(t[tx][ty + i]);
}

// ---------------------------------------------------------------------------
// WIDE fp16 GEMM for QKV: CTA 128x256, 256 threads (8 warps 2x4),
// warp tile 64x64, BK=32, 3-stage cp.async, ldmatrix fragments.
// mode: 1 = fp16 out, 2 = fp16 out * QSCALE
// ---------------------------------------------------------------------------
#define WAP 40
#define WASTG (128 * WAP)                 // A stage halves
#define WBSTG (256 * WAP)                 // B stage halves
#define WSTG  (WASTG + WBSTG)             // 15360 halves / stage
#define WSMEM (3 * WSTG * 2)              // 92160 bytes

__global__ __launch_bounds__(256, 2) void gemm16_qkv(
    const __half* __restrict__ x,
    const __half* __restrict__ Wq, const float* __restrict__ bq,
    const __half* __restrict__ Wk, const float* __restrict__ bk,
    const __half* __restrict__ Wv, const float* __restrict__ bv,
    __half* __restrict__ qp, __half* __restrict__ kp, __half* __restrict__ vp)
{
    const int z = blockIdx.z;
    const __half* Wt = (z == 0) ? Wq : (z == 1) ? Wk : Wv;
    const float* bias = (z == 0) ? bq : (z == 1) ? bk : bv;
    __half* C        = (z == 0) ? qp : (z == 1) ? kp : vp;
    const int mode   = (z == 0) ? 2 : 1;

    extern __shared__ __half wsm[];
    const int tid  = threadIdx.x;
    const int lane = tid & 31;
    const int warp = tid >> 5;
    const int gid  = lane >> 2;
    const int tig  = lane & 3;
    const int wm   = warp >> 2;      // 0..1
    const int wn   = warp & 3;       // 0..3
    const int m0   = blockIdx.y * 128;
    const int n0   = blockIdx.x * 256;

    const uint32_t s_base = (uint32_t)__cvta_generic_to_shared(wsm);

    // staging: A 128 rows x 32 halves (2 cp16/thread); B 256 rows x 32 (4 cp16)
    const int arow = tid >> 1;
    const int acol = (tid & 1) * 16;

    const int arow_f = wm * 64 + (lane & 7) + ((lane >> 3) & 1) * 8;
    const int acol_f = ((lane >> 4) & 1) * 8;
    const int brow_f = wn * 64 + (lane & 7) + ((lane >> 4) & 1) * 8;
    const int bcol_f = ((lane >> 3) & 1) * 8;

    float acc[4][8][4] = {};
    const int nt = EE / 32;

    #pragma unroll
    for (int s = 0; s < 2; s++) {
        const __half* ag = &x [(size_t)(m0 + arow) * EE + s * 32 + acol];
        const __half* bg = &Wt[(size_t)(n0 + tid) * EE + s * 32];
        uint32_t ad = s_base + (s * WSTG + arow * WAP + acol) * 2;
        uint32_t bd = s_base + (s * WSTG + WASTG + tid * WAP) * 2;
        cp16(ad,      ag);     cp16(ad + 16, ag + 8);
        #pragma unroll
        for (int c = 0; c < 4; c++)
            cp16(bd + c * 16, bg + c * 8);
        cp_commit();
    }

    for (int kt = 0; kt < nt; kt++) {
        cp_wait<1>();
        __syncthreads();

        if (kt + 2 < nt) {
            const int s = (kt + 2) % 3;
            const __half* ag = &x [(size_t)(m0 + arow) * EE + (kt + 2) * 32 + acol];
            const __half* bg = &Wt[(size_t)(n0 + tid) * EE + (kt + 2) * 32];
            uint32_t ad = s_base + (s * WSTG + arow * WAP + acol) * 2;
            uint32_t bd = s_base + (s * WSTG + WASTG + tid * WAP) * 2;
            cp16(ad,      ag);     cp16(ad + 16, ag + 8);
            #pragma unroll
            for (int c = 0; c < 4; c++)
                cp16(bd + c * 16, bg + c * 8);
        }
        cp_commit();

        const uint32_t as_s = s_base + ((kt % 3) * WSTG) * 2;
        const uint32_t bs_s = s_base + ((kt % 3) * WSTG + WASTG) * 2;

        #pragma unroll
        for (int ks = 0; ks < 2; ks++) {
            uint32_t af[4][4];
            #pragma unroll
            for (int i = 0; i < 4; i++)
                ldsm4(af[i][0], af[i][1], af[i][2], af[i][3],
                      as_s + (uint32_t)((arow_f + i * 16) * WAP + ks * 16 + acol_f) * 2);
            #pragma unroll
            for (int jp = 0; jp < 4; jp++) {
                uint32_t b00, b01, b10, b11;
                ldsm4(b00, b01, b10, b11,
                      bs_s + (uint32_t)((brow_f + jp * 16) * WAP + ks * 16 + bcol_f) * 2);
                #pragma unroll
                for (int i = 0; i < 4; i++) {
                    mma16(acc[i][2 * jp    ], af[i], b00, b01);
                    mma16(acc[i][2 * jp + 1], af[i], b10, b11);
                }
            }
        }
    }

    #pragma unroll
    for (int i = 0; i < 4; i++) {
        int r = m0 + wm * 64 + i * 16 + gid;
        #pragma unroll
        for (int j = 0; j < 8; j++) {
            int c = n0 + wn * 64 + j * 8 + 2 * tig;
            float2 bb = *(const float2*)&bias[c];
            float v00 = acc[i][j][0] + bb.x;
            float v01 = acc[i][j][1] + bb.y;
            float v10 = acc[i][j][2] + bb.x;
            float v11 = acc[i][j][3] + bb.y;
            if (mode == 2) { v00 *= QSCALE; v01 *= QSCALE; v10 *= QSCALE; v11 *= QSCALE; }
            *(__half2*)&C[(size_t)r * EE + c]       = __floats2half2_rn(v00, v01);
            *(__half2*)&C[(size_t)(r + 8) * EE + c] = __floats2half2_rn(v10, v11);
        }
    }
}

// ---------------------------------------------------------------------------
// Narrow fp16 GEMM (output projection): CTA 128x128, 128 threads,
// warp tile 64x64, BK=32, 3-stage, ldmatrix. fp32 output.
// ---------------------------------------------------------------------------
#define HAP 40
#define HSTG (128 * HAP)
#define HSMEM (3 * 2 * HSTG * 2)   // 61440 bytes

__global__ __launch_bounds__(128) void gemm16_out(
    const __half* __restrict__ A, const __half* __restrict__ Wt,
    const float* __restrict__ bias, float* __restrict__ C)
{
    extern __shared__ __half hsm[];
    __half* As = hsm;
    __half* Bs = hsm + 3 * HSTG;

    const int tid  = threadIdx.x;
    const int lane = tid & 31;
    const int warp = tid >> 5;
    const int gid  = lane >> 2;
    const int tig  = lane & 3;
    const int wm   = warp >> 1;
    const int wn   = warp & 1;
    const int m0   = blockIdx.y * 128;
    const int n0   = blockIdx.x * 128;

    const uint32_t a_base = (uint32_t)__cvta_generic_to_shared(As);
    const uint32_t b_base = (uint32_t)__cvta_generic_to_shared(Bs);

    const int arow_f = wm * 64 + (lane & 7) + ((lane >> 3) & 1) * 8;
    const int acol_f = ((lane >> 4) & 1) * 8;
    const int brow_f = wn * 64 + (lane & 7) + ((lane >> 4) & 1) * 8;
    const int bcol_f = ((lane >> 3) & 1) * 8;

    float acc[4][8][4] = {};
    const int nt = EE / 32;

    #pragma unroll
    for (int s = 0; s < 2; s++) {
        const __half* ag = &A [(size_t)(m0 + tid) * EE + s * 32];
        const __half* bg = &Wt[(size_t)(n0 + tid) * EE + s * 32];
        uint32_t ad = a_base + (s * HSTG + tid * HAP) * 2;
        uint32_t bd = b_base + (s * HSTG + tid * HAP) * 2;
        #pragma unroll
        for (int c = 0; c < 4; c++) {
            cp16(ad + c * 16, ag + c * 8);
            cp16(bd + c * 16, bg + c * 8);
        }
        cp_commit();
    }

    for (int kt = 0; kt < nt; kt++) {
        cp_wait<1>();
        __syncthreads();

        if (kt + 2 < nt) {
            const int s = (kt + 2) % 3;
            const __half* ag = &A [(size_t)(m0 + tid) * EE + (kt + 2) * 32];
            const __half* bg = &Wt[(size_t)(n0 + tid) * EE + (kt + 2) * 32];
            uint32_t ad = a_base + (s * HSTG + tid * HAP) * 2;
            uint32_t bd = b_base + (s * HSTG + tid * HAP) * 2;
            #pragma unroll
            for (int c = 0; c < 4; c++) {
                cp16(ad + c * 16, ag + c * 8);
                cp16(bd + c * 16, bg + c * 8);
            }
        }
        cp_commit();

        const uint32_t as_s = a_base + (kt % 3) * HSTG * 2;
        const uint32_t bs_s = b_base + (kt % 3) * HSTG * 2;

        #pragma unroll
        for (int ks = 0; ks < 2; ks++) {
            uint32_t af[4][4];
            #pragma unroll
            for (int i = 0; i < 4; i++)
                ldsm4(af[i][0], af[i][1], af[i][2], af[i][3],
                      as_s + (uint32_t)((arow_f + i * 16) * HAP + ks * 16 + acol_f) * 2);
            #pragma unroll
            for (int jp = 0; jp < 4; jp++) {
                uint32_t b00, b01, b10, b11;
                ldsm4(b00, b01, b10, b11,
                      bs_s + (uint32_t)((brow_f + jp * 16) * HAP + ks * 16 + bcol_f) * 2);
                #pragma unroll
                for (int i = 0; i < 4; i++) {
                    mma16(acc[i][2 * jp    ], af[i], b00, b01);
                    mma16(acc[i][2 * jp + 1], af[i], b10, b11);
                }
            }
        }
    }

    #pragma unroll
    for (int i = 0; i < 4; i++) {
        int r = m0 + wm * 64 + i * 16 + gid;
        #pragma unroll
        for (int j = 0; j < 8; j++) {
            int c = n0 + wn * 64 + j * 8 + 2 * tig;
            float2 bb = *(const float2*)&bias[c];
            *(float2*)&C[(size_t)r * EE + c] =
                make_float2(acc[i][j][0] + bb.x, acc[i][j][1] + bb.y);
            *(float2*)&C[(size_t)(r + 8) * EE + c] =
                make_float2(acc[i][j][2] + bb.x, acc[i][j][3] + bb.y);
        }
    }
}

// ---------------------------------------------------------------------------
// fp16 flash attention (unchanged from R12 passing version)
// ---------------------------------------------------------------------------
#define KPH 72
#define STAGE_H (2 * 64 * KPH)
#define FSMEM (3 * STAGE_H * 2)           // 55296 bytes

__global__ __launch_bounds__(256, 2) void flash16(
    const __half* __restrict__ Qg, const __half* __restrict__ Kg,
    const __half* __restrict__ Vg, __half* __restrict__ ctx)
{
    extern __shared__ __half fsm[];

    const int tid  = threadIdx.x;
    const int lane = tid & 31;
    const int warp = tid >> 5;
    const int gid  = lane >> 2;
    const int tig  = lane & 3;
    const int qt2  = (int)gridDim.x - 1 - (int)blockIdx.x;
    const int h    = blockIdx.y;
    const int b    = blockIdx.z;
    const int q0   = qt2 * 128;
    const int wloc = (warp >> 2) * 64 + (warp & 3) * 16;
    const int wbase = q0 + wloc;
    const int nt   = 2 * qt2 + 2;

    const size_t base = (size_t)b * SS * EE + (size_t)h * DD;
    const uint32_t smem0 = (uint32_t)__cvta_generic_to_shared(fsm);

    const int srow = tid >> 2;
    const int scol = (tid & 3) * 16;
    const uint32_t soff = (uint32_t)(srow * KPH + scol) * 2;

    const int qrow_f = wloc + (lane & 7) + ((lane >> 3) & 1) * 8;
    const int qcol_f = ((lane >> 4) & 1) * 8;
    const int krow_f = (lane & 7) + ((lane >> 4) & 1) * 8;
    const int kcol_f = ((lane >> 3) & 1) * 8;
    const int vrow_t = (lane & 7) + ((lane >> 3) & 1) * 8;
    const int vcol_t = ((lane >> 4) & 1) * 8;

    {
        const int qrow = tid >> 1;
        const int qh   = (tid & 1) * 32;
        const __half* qsrc = &Qg[base + (size_t)(q0 + qrow) * EE + qh];
        uint32_t qd = smem0 + (uint32_t)(qrow * KPH + qh) * 2;
        #pragma unroll
        for (int c = 0; c < 4; c++)
            cp16(qd + c * 16, qsrc + c * 8);
        cp_commit();
    }
    cp_wait<0>();
    __syncthreads();

    uint32_t qf[4][4];
    #pragma unroll
    for (int ks = 0; ks < 4; ks++)
        ldsm4(qf[ks][0], qf[ks][1], qf[ks][2], qf[ks][3],
              smem0 + (uint32_t)(qrow_f * KPH + ks * 16 + qcol_f) * 2);
    __syncthreads();

    #pragma unroll
    for (int pt = 0; pt < 2; pt++) {
        if (pt < nt) {
            const uint32_t st = smem0 + (uint32_t)(pt * STAGE_H) * 2;
            const __half* kg = &Kg[base + (size_t)(pt * 64 + srow) * EE + scol];
            const __half* vg = &Vg[base + (size_t)(pt * 64 + srow) * EE + scol];
            cp16(st + soff,      kg);   cp16(st + soff + 16, kg + 8);
            cp16(st + (uint32_t)(64 * KPH) * 2 + soff,      vg);
            cp16(st + (uint32_t)(64 * KPH) * 2 + soff + 16, vg + 8);
        }
        cp_commit();
    }

    float oacc[8][4] = {};
    float m0r = -CUDART_INF_F, m1r = -CUDART_INF_F;
    float l0 = 0.f, l1 = 0.f;
    const int r0g = wbase + gid;
    const int r1g = r0g + 8;

    for (int kt = 0; kt < nt; kt++) {
        const int k0 = kt * 64;

        __syncthreads();

        if (kt + 2 < nt) {
            const int kn = (kt + 2) * 64;
            const uint32_t st = smem0 + (uint32_t)(((kt + 2) % 3) * STAGE_H) * 2;
            const __half* kg = &Kg[base + (size_t)(kn + srow) * EE + scol];
            const __half* vg = &Vg[base + (size_t)(kn + srow) * EE + scol];
            cp16(st + soff,      kg);   cp16(st + soff + 16, kg + 8);
            cp16(st + (uint32_t)(64 * KPH) * 2 + soff,      vg);
            cp16(st + (uint32_t)(64 * KPH) * 2 + soff + 16, vg + 8);
        }
        cp_commit();
        cp_wait<2>();
        __syncthreads();

        if (k0 <= wbase + 15) {
            const uint32_t KS_ = smem0 + (uint32_t)((kt % 3) * STAGE_H) * 2;
            const uint32_t VS_ = KS_ + (uint32_t)(64 * KPH) * 2;

            float sacc[8][4] = {};
            #pragma unroll
            for (int tp = 0; tp < 4; tp++) {
                #pragma unroll
                for (int ks = 0; ks < 4; ks++) {
                    uint32_t b00, b01, b10, b11;
                    ldsm4(b00, b01, b10, b11,
                          KS_ + (uint32_t)((krow_f + tp * 16) * KPH + ks * 16 + kcol_f) * 2);
                    mma16(sacc[2 * tp    ], qf[ks], b00, b01);
                    mma16(sacc[2 * tp + 1], qf[ks], b10, b11);
                }
            }

            if (k0 + 63 > wbase) {
                #pragma unroll
                for (int t = 0; t < 8; t++) {
                    int c = k0 + t * 8 + 2 * tig;
                    if (c     > r0g) sacc[t][0] = -CUDART_INF_F;
                    if (c + 1 > r0g) sacc[t][1] = -CUDART_INF_F;
                    if (c     > r1g) sacc[t][2] = -CUDART_INF_F;
                    if (c + 1 > r1g) sacc[t][3] = -CUDART_INF_F;
                }
            }

            float vm0 = -CUDART_INF_F, vm1 = -CUDART_INF_F;
            #pragma unroll
            for (int t = 0; t < 8; t++) {
                vm0 = fmaxf(vm0, fmaxf(sacc[t][0], sacc[t][1]));
                vm1 = fmaxf(vm1, fmaxf(sacc[t][2], sacc[t][3]));
            }
            vm0 = fmaxf(vm0, __shfl_xor_sync(0xffffffffu, vm0, 1));
            vm0 = fmaxf(vm0, __shfl_xor_sync(0xffffffffu, vm0, 2));
            vm1 = fmaxf(vm1, __shfl_xor_sync(0xffffffffu, vm1, 1));
            vm1 = fmaxf(vm1, __shfl_xor_sync(0xffffffffu, vm1, 2));

            float mn0 = fmaxf(m0r, vm0), mn1 = fmaxf(m1r, vm1);
            float al0 = ex2f(m0r - mn0), al1 = ex2f(m1r - mn1);

            uint32_t pf[4][4];
            float sum0 = 0.f, sum1 = 0.f;
            #pragma unroll
            for (int ks = 0; ks < 4; ks++) {
                #pragma unroll
                for (int u = 0; u < 2; u++) {
                    const float* s = sacc[2 * ks + u];
                    uint32_t e01 = ex2_h2(s[0] - mn0, s[1] - mn0);
                    uint32_t e23 = ex2_h2(s[2] - mn1, s[3] - mn1);
                    pf[ks][2 * u    ] = e01;
                    pf[ks][2 * u + 1] = e23;
                    float2 f01 = __half22float2(*(__half2*)&e01);
                    float2 f23 = __half22float2(*(__half2*)&e23);
                    sum0 += f01.x + f01.y;
                    sum1 += f23.x + f23.y;
                }
            }
            sum0 += __shfl_xor_sync(0xffffffffu, sum0, 1);
            sum0 += __shfl_xor_sync(0xffffffffu, sum0, 2);
            sum1 += __shfl_xor_sync(0xffffffffu, sum1, 1);
            sum1 += __shfl_xor_sync(0xffffffffu, sum1, 2);

            l0 = l0 * al0 + sum0;  m0r = mn0;
            l1 = l1 * al1 + sum1;  m1r = mn1;
            #pragma unroll
            for (int dt = 0; dt < 8; dt++) {
                oacc[dt][0] *= al0; oacc[dt][1] *= al0;
                oacc[dt][2] *= al1; oacc[dt][3] *= al1;
            }

            #pragma unroll
            for (int ks = 0; ks < 4; ks++) {
                #pragma unroll
                for (int dp = 0; dp < 4; dp++) {
                    uint32_t b00, b01, b10, b11;
                    ldsm4t(b00, b01, b10, b11,
                           VS_ + (uint32_t)((ks * 16 + vrow_t) * KPH + dp * 16 + vcol_t) * 2);
                    mma16(oacc[2 * dp    ], pf[ks], b00, b01);
                    mma16(oacc[2 * dp + 1], pf[ks], b10, b11);
                }
            }
        }
    }

    float inv0 = 1.f / l0, inv1 = 1.f / l1;
    #pragma unroll
    for (int dt = 0; dt < 8; dt++) {
        int c = dt * 8 + 2 * tig;
        *(__half2*)&ctx[base + (size_t)r0g * EE + c] =
            __floats2half2_rn(oacc[dt][0] * inv0, oacc[dt][1] * inv0);
        *(__half2*)&ctx[base + (size_t)r1g * EE + c] =
            __floats2half2_rn(oacc[dt][2] * inv1, oacc[dt][3] * inv1);
    }
}

// ---------------------------------------------------------------------------
// Launch
// ---------------------------------------------------------------------------
extern "C" void kernel_launch(void* const* d_in, const int* in_sizes, int n_in,
                              void* d_out, int out_size)
{
    (void)in_sizes; (void)n_in; (void)out_size;
    const float* x  = (const float*)d_in[0];
    const float* Wq = (const float*)d_in[1];
    const float* bq = (const float*)d_in[2];
    const float* Wk = (const float*)d_in[3];
    const float* bk = (const float*)d_in[4];
    const float* Wv = (const float*)d_in[5];
    const float* bv = (const float*)d_in[6];
    const float* Wo = (const float*)d_in[7];
    const float* bo = (const float*)d_in[8];
    float* out = (float*)d_out;

    __half *qp, *kp, *vp, *cp, *xt, *wq, *wk, *wv, *wo;
    cudaGetSymbolAddress((void**)&qp,  g_q);
    cudaGetSymbolAddress((void**)&kp,  g_k);
    cudaGetSymbolAddress((void**)&vp,  g_v);
    cudaGetSymbolAddress((void**)&cp,  g_ctx);
    cudaGetSymbolAddress((void**)&xt,  g_xt);
    cudaGetSymbolAddress((void**)&wq,  g_wq);
    cudaGetSymbolAddress((void**)&wk,  g_wk);
    cudaGetSymbolAddress((void**)&wv,  g_wv);
    cudaGetSymbolAddress((void**)&wo,  g_wo);

    const int xn4 = BB * SS * EE / 4;
    cvt_h<<<xn4 / 256, 256>>>(x, xt, xn4);
    dim3 tb(32, 8);
    transcvt_w4<<<dim3(EE / 32, EE / 32, 4), tb>>>(Wq, Wk, Wv, Wo, wq, wk, wv, wo);

    cudaFuncSetAttribute(gemm16_qkv, cudaFuncAttributeMaxDynamicSharedMemorySize, WSMEM);
    cudaFuncSetAttribute(gemm16_out, cudaFuncAttributeMaxDynamicSharedMemorySize, HSMEM);
    cudaFuncSetAttribute(flash16, cudaFuncAttributeMaxDynamicSharedMemorySize, FSMEM);

    dim3 gqkv(EE / 256, (BB * SS) / 128, 3);   // (4, 32, 3)
    gemm16_qkv<<<gqkv, 256, WSMEM>>>(xt, wq, bq, wk, bk, wv, bv, qp, kp, vp);

    flash16<<<dim3(SS / 128, HH, BB), 256, FSMEM>>>(qp, kp, vp, cp);

    dim3 go(EE / 128, (BB * SS) / 128);        // (8, 32)
    gemm16_out<<<go, 128, HSMEM>>>(cp, wo, bo, out);
}

// round 14
// speedup vs baseline: 1.7113x; 1.7113x over previous
#include <cuda_runtime.h>
#include <cuda_fp16.h>
#include <math_constants.h>
#include <cstdint>

// Problem constants
#define BB 2
#define SS 2048
#define EE 1024
#define HH 16
#define DD 64

// Scratch (device globals — allocation-free rule)
__device__ __half g_q [BB * SS * EE];
__device__ __half g_k [BB * SS * EE];
__device__ __half g_v [BB * SS * EE];
__device__ __half g_ctx[BB * SS * EE];
__device__ __half g_xt[BB * SS * EE];        // x in fp16
__device__ __half g_wq[EE * EE];             // W^T in fp16: [N][K]
__device__ __half g_wk[EE * EE];
__device__ __half g_wv[EE * EE];
__device__ __half g_wo[EE * EE];

// Q pre-scale: (1/sqrt(64)) * log2(e)  -> scores in log2 units
#define QSCALE 0.1803368801111204f

// ---------------------------------------------------------------------------
// helpers
// ---------------------------------------------------------------------------
__device__ __forceinline__ void mma16(
    float* c, const uint32_t* a, uint32_t b0, uint32_t b1)
{
    asm volatile(
        "mma.sync.aligned.m16n8k16.row.col.f32.f16.f16.f32 "
        "{%0,%1,%2,%3},{%4,%5,%6,%7},{%8,%9},{%0,%1,%2,%3};\n"
        : "+f"(c[0]), "+f"(c[1]), "+f"(c[2]), "+f"(c[3])
        : "r"(a[0]), "r"(a[1]), "r"(a[2]), "r"(a[3]), "r"(b0), "r"(b1));
}

__device__ __forceinline__ void ldsm4(
    uint32_t& r0, uint32_t& r1, uint32_t& r2, uint32_t& r3, uint32_t addr)
{
    asm volatile(
        "ldmatrix.sync.aligned.m8n8.x4.shared.b16 {%0,%1,%2,%3}, [%4];"
        : "=r"(r0), "=r"(r1), "=r"(r2), "=r"(r3) : "r"(addr));
}

__device__ __forceinline__ void ldsm4t(
    uint32_t& r0, uint32_t& r1, uint32_t& r2, uint32_t& r3, uint32_t addr)
{
    asm volatile(
        "ldmatrix.sync.aligned.m8n8.x4.trans.shared.b16 {%0,%1,%2,%3}, [%4];"
        : "=r"(r0), "=r"(r1), "=r"(r2), "=r"(r3) : "r"(addr));
}

__device__ __forceinline__ float ex2f(float x) {
    float r;
    asm("ex2.approx.f32 %0, %1;" : "=f"(r) : "f"(x));
    return r;
}

__device__ __forceinline__ uint32_t ex2_h2(float a, float b) {
    __half2 h = __floats2half2_rn(a, b);
    uint32_t r;
    asm("ex2.approx.f16x2 %0, %1;" : "=r"(r) : "r"(*(uint32_t*)&h));
    return r;
}

__device__ __forceinline__ void cp16(uint32_t smem_dst, const void* gsrc) {
    asm volatile("cp.async.cg.shared.global [%0], [%1], 16;\n"
                 :: "r"(smem_dst), "l"(gsrc));
}
__device__ __forceinline__ void cp_commit() {
    asm volatile("cp.async.commit_group;\n");
}
template<int N>
__device__ __forceinline__ void cp_wait() {
    asm volatile("cp.async.wait_group %0;\n" :: "n"(N));
}

// ---------------------------------------------------------------------------
// prologue conversions
// ---------------------------------------------------------------------------
__global__ __launch_bounds__(256) void cvt_h(
    const float* __restrict__ src, __half* __restrict__ dst, int n4)
{
    int i = blockIdx.x * blockDim.x + threadIdx.x;
    if (i < n4) {
        float4 v = ((const float4*)src)[i];
        __half2 h0 = __floats2half2_rn(v.x, v.y);
        __half2 h1 = __floats2half2_rn(v.z, v.w);
        *(uint2*)&dst[4 * i] = make_uint2(*(uint32_t*)&h0, *(uint32_t*)&h1);
    }
}

__global__ __launch_bounds__(256) void transcvt_w4(
    const float* __restrict__ W0, const float* __restrict__ W1,
    const float* __restrict__ W2, const float* __restrict__ W3,
    __half* __restrict__ T0, __half* __restrict__ T1,
    __half* __restrict__ T2, __half* __restrict__ T3)
{
    const int z = blockIdx.z;
    const float* W = (z == 0) ? W0 : (z == 1) ? W1 : (z == 2) ? W2 : W3;
    __half* Wt     = (z == 0) ? T0 : (z == 1) ? T1 : (z == 2) ? T2 : T3;

    __shared__ float t[32][33];
    const int n0 = blockIdx.x * 32;
    const int k0 = blockIdx.y * 32;
    const int tx = threadIdx.x;
    const int ty = threadIdx.y;
    #pragma unroll
    for (int i = 0; i < 32; i += 8)
        t[ty + i][tx] = W[(size_t)(k0 + ty + i) * EE + n0 + tx];
    __syncthreads();
    #pragma unroll
    for (int i = 0; i < 32; i += 8)
        Wt[(size_t)(n0 + ty + i) * EE + k0 + tx] = __float2half(t[tx][ty + i]);
}

// ---------------------------------------------------------------------------
// fp16 GEMM: C[4096,1024] = A @ W + bias, W as W^T fp16.
// CTA 128x128, 256 threads (8 warps as 4x2), warp tile 32x64, BK=32,
// 3-stage cp.async, ldmatrix fragments. smem 61440 B -> 3 CTA/SM by smem,
// 2 by __launch_bounds__(256,2) regs (16 warps/SM).
// mode: 0 = fp32 out, 1 = fp16 out, 2 = fp16 out * QSCALE
// ---------------------------------------------------------------------------
#define HAP 40
#define HSTG (128 * HAP)
#define HSMEM (3 * 2 * HSTG * 2)   // 61440 bytes

__device__ __forceinline__ void gemm16_body(
    const __half* __restrict__ A, const __half* __restrict__ Wt,
    const float* __restrict__ bias, void* Cv, int mode)
{
    extern __shared__ __half hsm[];
    __half* As = hsm;
    __half* Bs = hsm + 3 * HSTG;

    const int tid  = threadIdx.x;
    const int lane = tid & 31;
    const int warp = tid >> 5;      // 0..7
    const int gid  = lane >> 2;
    const int tig  = lane & 3;
    const int wm   = warp >> 1;     // 0..3 (M dir, 32 rows each)
    const int wn   = warp & 1;      // 0..1 (N dir, 64 cols each)
    const int m0   = blockIdx.y * 128;
    const int n0   = blockIdx.x * 128;

    const uint32_t a_base = (uint32_t)__cvta_generic_to_shared(As);
    const uint32_t b_base = (uint32_t)__cvta_generic_to_shared(Bs);

    // staging: 256 threads, A 128 rows x 32 halves => 16 halves (1 cp16x2... )
    // each thread: row tid>>1, half (tid&1)*16, 1x2 cp16 for A and same for B
    const int srow = tid >> 1;
    const int scol = (tid & 1) * 16;

    // fragment lane offsets
    const int arow_f = wm * 32 + (lane & 7) + ((lane >> 3) & 1) * 8;
    const int acol_f = ((lane >> 4) & 1) * 8;
    const int brow_f = wn * 64 + (lane & 7) + ((lane >> 4) & 1) * 8;
    const int bcol_f = ((lane >> 3) & 1) * 8;

    float acc[2][8][4] = {};
    const int nt = EE / 32;

    #pragma unroll
    for (int s = 0; s < 2; s++) {
        const __half* ag = &A [(size_t)(m0 + srow) * EE + s * 32 + scol];
        const __half* bg = &Wt[(size_t)(n0 + srow) * EE + s * 32 + scol];
        uint32_t ad = a_base + (s * HSTG + srow * HAP + scol) * 2;
        uint32_t bd = b_base + (s * HSTG + srow * HAP + scol) * 2;
        cp16(ad,      ag);   cp16(ad + 16, ag + 8);
        cp16(bd,      bg);   cp16(bd + 16, bg + 8);
        cp_commit();
    }

    for (int kt = 0; kt < nt; kt++) {
        cp_wait<1>();
        __syncthreads();

        if (kt + 2 < nt) {
            const int s = (kt + 2) % 3;
            const __half* ag = &A [(size_t)(m0 + srow) * EE + (kt + 2) * 32 + scol];
            const __half* bg = &Wt[(size_t)(n0 + srow) * EE + (kt + 2) * 32 + scol];
            uint32_t ad = a_base + (s * HSTG + srow * HAP + scol) * 2;
            uint32_t bd = b_base + (s * HSTG + srow * HAP + scol) * 2;
            cp16(ad,      ag);   cp16(ad + 16, ag + 8);
            cp16(bd,      bg);   cp16(bd + 16, bg + 8);
        }
        cp_commit();

        const uint32_t as_s = a_base + (kt % 3) * HSTG * 2;
        const uint32_t bs_s = b_base + (kt % 3) * HSTG * 2;

        #pragma unroll
        for (int ks = 0; ks < 2; ks++) {
            uint32_t af[2][4];
            // one x4 ldsm covers rows wm*32 + {0..15} (i=0) / +16 (i=1)
            #pragma unroll
            for (int i = 0; i < 2; i++)
                ldsm4(af[i][0], af[i][1], af[i][2], af[i][3],
                      as_s + (uint32_t)((arow_f + i * 16) * HAP + ks * 16 + acol_f) * 2);
            #pragma unroll
            for (int jp = 0; jp < 4; jp++) {
                uint32_t b00, b01, b10, b11;
                ldsm4(b00, b01, b10, b11,
                      bs_s + (uint32_t)((brow_f + jp * 16) * HAP + ks * 16 + bcol_f) * 2);
                #pragma unroll
                for (int i = 0; i < 2; i++) {
                    mma16(acc[i][2 * jp    ], af[i], b00, b01);
                    mma16(acc[i][2 * jp + 1], af[i], b10, b11);
                }
            }
        }
    }

    #pragma unroll
    for (int i = 0; i < 2; i++) {
        int r = m0 + wm * 32 + i * 16 + gid;
        #pragma unroll
        for (int j = 0; j < 8; j++) {
            int c = n0 + wn * 64 + j * 8 + 2 * tig;
            float2 bb = *(const float2*)&bias[c];
            float v00 = acc[i][j][0] + bb.x;
            float v01 = acc[i][j][1] + bb.y;
            float v10 = acc[i][j][2] + bb.x;
            float v11 = acc[i][j][3] + bb.y;
            if (mode == 0) {
                float* C = (float*)Cv;
                *(float2*)&C[(size_t)r * EE + c]       = make_float2(v00, v01);
                *(float2*)&C[(size_t)(r + 8) * EE + c] = make_float2(v10, v11);
            } else {
                if (mode == 2) { v00 *= QSCALE; v01 *= QSCALE; v10 *= QSCALE; v11 *= QSCALE; }
                __half* C = (__half*)Cv;
                *(__half2*)&C[(size_t)r * EE + c]       = __floats2half2_rn(v00, v01);
                *(__half2*)&C[(size_t)(r + 8) * EE + c] = __floats2half2_rn(v10, v11);
            }
        }
    }
}

__global__ __launch_bounds__(256, 2) void gemm16_qkv(
    const __half* __restrict__ x,
    const __half* __restrict__ Wq, const float* __restrict__ bq,
    const __half* __restrict__ Wk, const float* __restrict__ bk,
    const __half* __restrict__ Wv, const float* __restrict__ bv,
    __half* __restrict__ qp, __half* __restrict__ kp, __half* __restrict__ vp)
{
    const int z = blockIdx.z;
    const __half* W  = (z == 0) ? Wq : (z == 1) ? Wk : Wv;
    const float* bb  = (z == 0) ? bq : (z == 1) ? bk : bv;
    __half* C        = (z == 0) ? qp : (z == 1) ? kp : vp;
    gemm16_body(x, W, bb, C, (z == 0) ? 2 : 1);
}

__global__ __launch_bounds__(256, 2) void gemm16_out(
    const __half* __restrict__ A, const __half* __restrict__ Wt,
    const float* __restrict__ bias, float* __restrict__ C)
{
    gemm16_body(A, Wt, bias, C, 0);
}

// ---------------------------------------------------------------------------
// fp16 flash attention (unchanged from R12 passing version)
// ---------------------------------------------------------------------------
#define KPH 72
#define STAGE_H (2 * 64 * KPH)
#define FSMEM (3 * STAGE_H * 2)           // 55296 bytes

__global__ __launch_bounds__(256, 2) void flash16(
    const __half* __restrict__ Qg, const __half* __restrict__ Kg,
    const __half* __restrict__ Vg, __half* __restrict__ ctx)
{
    extern __shared__ __half fsm[];

    const int tid  = threadIdx.x;
    const int lane = tid & 31;
    const int warp = tid >> 5;
    const int gid  = lane >> 2;
    const int tig  = lane & 3;
    const int qt2  = (int)gridDim.x - 1 - (int)blockIdx.x;
    const int h    = blockIdx.y;
    const int b    = blockIdx.z;
    const int q0   = qt2 * 128;
    const int wloc = (warp >> 2) * 64 + (warp & 3) * 16;
    const int wbase = q0 + wloc;
    const int nt   = 2 * qt2 + 2;

    const size_t base = (size_t)b * SS * EE + (size_t)h * DD;
    const uint32_t smem0 = (uint32_t)__cvta_generic_to_shared(fsm);

    const int srow = tid >> 2;
    const int scol = (tid & 3) * 16;
    const uint32_t soff = (uint32_t)(srow * KPH + scol) * 2;

    const int qrow_f = wloc + (lane & 7) + ((lane >> 3) & 1) * 8;
    const int qcol_f = ((lane >> 4) & 1) * 8;
    const int krow_f = (lane & 7) + ((lane >> 4) & 1) * 8;
    const int kcol_f = ((lane >> 3) & 1) * 8;
    const int vrow_t = (lane & 7) + ((lane >> 3) & 1) * 8;
    const int vcol_t = ((lane >> 4) & 1) * 8;

    {
        const int qrow = tid >> 1;
        const int qh   = (tid & 1) * 32;
        const __half* qsrc = &Qg[base + (size_t)(q0 + qrow) * EE + qh];
        uint32_t qd = smem0 + (uint32_t)(qrow * KPH + qh) * 2;
        #pragma unroll
        for (int c = 0; c < 4; c++)
            cp16(qd + c * 16, qsrc + c * 8);
        cp_commit();
    }
    cp_wait<0>();
    __syncthreads();

    uint32_t qf[4][4];
    #pragma unroll
    for (int ks = 0; ks < 4; ks++)
        ldsm4(qf[ks][0], qf[ks][1], qf[ks][2], qf[ks][3],
              smem0 + (uint32_t)(qrow_f * KPH + ks * 16 + qcol_f) * 2);
    __syncthreads();

    #pragma unroll
    for (int pt = 0; pt < 2; pt++) {
        if (pt < nt) {
            const uint32_t st = smem0 + (uint32_t)(pt * STAGE_H) * 2;
            const __half* kg = &Kg[base + (size_t)(pt * 64 + srow) * EE + scol];
            const __half* vg = &Vg[base + (size_t)(pt * 64 + srow) * EE + scol];
            cp16(st + soff,      kg);   cp16(st + soff + 16, kg + 8);
            cp16(st + (uint32_t)(64 * KPH) * 2 + soff,      vg);
            cp16(st + (uint32_t)(64 * KPH) * 2 + soff + 16, vg + 8);
        }
        cp_commit();
    }

    float oacc[8][4] = {};
    float m0r = -CUDART_INF_F, m1r = -CUDART_INF_F;
    float l0 = 0.f, l1 = 0.f;
    const int r0g = wbase + gid;
    const int r1g = r0g + 8;

    for (int kt = 0; kt < nt; kt++) {
        const int k0 = kt * 64;

        __syncthreads();

        if (kt + 2 < nt) {
            const int kn = (kt + 2) * 64;
            const uint32_t st = smem0 + (uint32_t)(((kt + 2) % 3) * STAGE_H) * 2;
            const __half* kg = &Kg[base + (size_t)(kn + srow) * EE + scol];
            const __half* vg = &Vg[base + (size_t)(kn + srow) * EE + scol];
            cp16(st + soff,      kg);   cp16(st + soff + 16, kg + 8);
            cp16(st + (uint32_t)(64 * KPH) * 2 + soff,      vg);
            cp16(st + (uint32_t)(64 * KPH) * 2 + soff + 16, vg + 8);
        }
        cp_commit();
        cp_wait<2>();
        __syncthreads();

        if (k0 <= wbase + 15) {
            const uint32_t KS_ = smem0 + (uint32_t)((kt % 3) * STAGE_H) * 2;
            const uint32_t VS_ = KS_ + (uint32_t)(64 * KPH) * 2;

            float sacc[8][4] = {};
            #pragma unroll
            for (int tp = 0; tp < 4; tp++) {
                #pragma unroll
                for (int ks = 0; ks < 4; ks++) {
                    uint32_t b00, b01, b10, b11;
                    ldsm4(b00, b01, b10, b11,
                          KS_ + (uint32_t)((krow_f + tp * 16) * KPH + ks * 16 + kcol_f) * 2);
                    mma16(sacc[2 * tp    ], qf[ks], b00, b01);
                    mma16(sacc[2 * tp + 1], qf[ks], b10, b11);
                }
            }

            if (k0 + 63 > wbase) {
                #pragma unroll
                for (int t = 0; t < 8; t++) {
                    int c = k0 + t * 8 + 2 * tig;
                    if (c     > r0g) sacc[t][0] = -CUDART_INF_F;
                    if (c + 1 > r0g) sacc[t][1] = -CUDART_INF_F;
                    if (c     > r1g) sacc[t][2] = -CUDART_INF_F;
                    if (c + 1 > r1g) sacc[t][3] = -CUDART_INF_F;
                }
            }

            float vm0 = -CUDART_INF_F, vm1 = -CUDART_INF_F;
            #pragma unroll
            for (int t = 0; t < 8; t++) {
                vm0 = fmaxf(vm0, fmaxf(sacc[t][0], sacc[t][1]));
                vm1 = fmaxf(vm1, fmaxf(sacc[t][2], sacc[t][3]));
            }
            vm0 = fmaxf(vm0, __shfl_xor_sync(0xffffffffu, vm0, 1));
            vm0 = fmaxf(vm0, __shfl_xor_sync(0xffffffffu, vm0, 2));
            vm1 = fmaxf(vm1, __shfl_xor_sync(0xffffffffu, vm1, 1));
            vm1 = fmaxf(vm1, __shfl_xor_sync(0xffffffffu, vm1, 2));

            float mn0 = fmaxf(m0r, vm0), mn1 = fmaxf(m1r, vm1);
            float al0 = ex2f(m0r - mn0), al1 = ex2f(m1r - mn1);

            uint32_t pf[4][4];
            float sum0 = 0.f, sum1 = 0.f;
            #pragma unroll
            for (int ks = 0; ks < 4; ks++) {
                #pragma unroll
                for (int u = 0; u < 2; u++) {
                    const float* s = sacc[2 * ks + u];
                    uint32_t e01 = ex2_h2(s[0] - mn0, s[1] - mn0);
                    uint32_t e23 = ex2_h2(s[2] - mn1, s[3] - mn1);
                    pf[ks][2 * u    ] = e01;
                    pf[ks][2 * u + 1] = e23;
                    float2 f01 = __half22float2(*(__half2*)&e01);
                    float2 f23 = __half22float2(*(__half2*)&e23);
                    sum0 += f01.x + f01.y;
                    sum1 += f23.x + f23.y;
                }
            }
            sum0 += __shfl_xor_sync(0xffffffffu, sum0, 1);
            sum0 += __shfl_xor_sync(0xffffffffu, sum0, 2);
            sum1 += __shfl_xor_sync(0xffffffffu, sum1, 1);
            sum1 += __shfl_xor_sync(0xffffffffu, sum1, 2);

            l0 = l0 * al0 + sum0;  m0r = mn0;
            l1 = l1 * al1 + sum1;  m1r = mn1;
            #pragma unroll
            for (int dt = 0; dt < 8; dt++) {
                oacc[dt][0] *= al0; oacc[dt][1] *= al0;
                oacc[dt][2] *= al1; oacc[dt][3] *= al1;
            }

            #pragma unroll
            for (int ks = 0; ks < 4; ks++) {
                #pragma unroll
                for (int dp = 0; dp < 4; dp++) {
                    uint32_t b00, b01, b10, b11;
                    ldsm4t(b00, b01, b10, b11,
                           VS_ + (uint32_t)((ks * 16 + vrow_t) * KPH + dp * 16 + vcol_t) * 2);
                    mma16(oacc[2 * dp    ], pf[ks], b00, b01);
                    mma16(oacc[2 * dp + 1], pf[ks], b10, b11);
                }
            }
        }
    }

    float inv0 = 1.f / l0, inv1 = 1.f / l1;
    #pragma unroll
    for (int dt = 0; dt < 8; dt++) {
        int c = dt * 8 + 2 * tig;
        *(__half2*)&ctx[base + (size_t)r0g * EE + c] =
            __floats2half2_rn(oacc[dt][0] * inv0, oacc[dt][1] * inv0);
        *(__half2*)&ctx[base + (size_t)r1g * EE + c] =
            __floats2half2_rn(oacc[dt][2] * inv1, oacc[dt][3] * inv1);
    }
}

// ---------------------------------------------------------------------------
// Launch
// ---------------------------------------------------------------------------
extern "C" void kernel_launch(void* const* d_in, const int* in_sizes, int n_in,
                              void* d_out, int out_size)
{
    (void)in_sizes; (void)n_in; (void)out_size;
    const float* x  = (const float*)d_in[0];
    const float* Wq = (const float*)d_in[1];
    const float* bq = (const float*)d_in[2];
    const float* Wk = (const float*)d_in[3];
    const float* bk = (const float*)d_in[4];
    const float* Wv = (const float*)d_in[5];
    const float* bv = (const float*)d_in[6];
    const float* Wo = (const float*)d_in[7];
    const float* bo = (const float*)d_in[8];
    float* out = (float*)d_out;

    __half *qp, *kp, *vp, *cp, *xt, *wq, *wk, *wv, *wo;
    cudaGetSymbolAddress((void**)&qp,  g_q);
    cudaGetSymbolAddress((void**)&kp,  g_k);
    cudaGetSymbolAddress((void**)&vp,  g_v);
    cudaGetSymbolAddress((void**)&cp,  g_ctx);
    cudaGetSymbolAddress((void**)&xt,  g_xt);
    cudaGetSymbolAddress((void**)&wq,  g_wq);
    cudaGetSymbolAddress((void**)&wk,  g_wk);
    cudaGetSymbolAddress((void**)&wv,  g_wv);
    cudaGetSymbolAddress((void**)&wo,  g_wo);

    const int xn4 = BB * SS * EE / 4;
    cvt_h<<<xn4 / 256, 256>>>(x, xt, xn4);
    dim3 tb(32, 8);
    transcvt_w4<<<dim3(EE / 32, EE / 32, 4), tb>>>(Wq, Wk, Wv, Wo, wq, wk, wv, wo);

    cudaFuncSetAttribute(gemm16_qkv, cudaFuncAttributeMaxDynamicSharedMemorySize, HSMEM);
    cudaFuncSetAttribute(gemm16_out, cudaFuncAttributeMaxDynamicSharedMemorySize, HSMEM);
    cudaFuncSetAttribute(flash16, cudaFuncAttributeMaxDynamicSharedMemorySize, FSMEM);

    dim3 gqkv(EE / 128, (BB * SS) / 128, 3);   // (8, 32, 3)
    gemm16_qkv<<<gqkv, 256, HSMEM>>>(xt, wq, bq, wk, bk, wv, bv, qp, kp, vp);

    flash16<<<dim3(SS / 128, HH, BB), 256, FSMEM>>>(qp, kp, vp, cp);

    dim3 go(EE / 128, (BB * SS) / 128);        // (8, 32)
    gemm16_out<<<go, 256, HSMEM>>>(cp, wo, bo, out);
}

// round 15
// speedup vs baseline: 1.7636x; 1.0306x over previous
#include <cuda_runtime.h>
#include <cuda_fp16.h>
#include <math_constants.h>
#include <cstdint>

// Problem constants
#define BB 2
#define SS 2048
#define EE 1024
#define HH 16
#define DD 64

// Scratch (device globals — allocation-free rule)
__device__ __half g_q [BB * SS * EE];
__device__ __half g_k [BB * SS * EE];
__device__ __half g_v [BB * SS * EE];
__device__ __half g_ctx[BB * SS * EE];
__device__ __half g_xt[BB * SS * EE];        // x in fp16
__device__ __half g_wq[EE * EE];             // W^T in fp16: [N][K]
__device__ __half g_wk[EE * EE];
__device__ __half g_wv[EE * EE];
__device__ __half g_wo[EE * EE];

// Q pre-scale: (1/sqrt(64)) * log2(e)  -> scores in log2 units
#define QSCALE 0.1803368801111204f

// ---------------------------------------------------------------------------
// helpers
// ---------------------------------------------------------------------------
__device__ __forceinline__ void mma16(
    float* c, const uint32_t* a, uint32_t b0, uint32_t b1)
{
    asm volatile(
        "mma.sync.aligned.m16n8k16.row.col.f32.f16.f16.f32 "
        "{%0,%1,%2,%3},{%4,%5,%6,%7},{%8,%9},{%0,%1,%2,%3};\n"
        : "+f"(c[0]), "+f"(c[1]), "+f"(c[2]), "+f"(c[3])
        : "r"(a[0]), "r"(a[1]), "r"(a[2]), "r"(a[3]), "r"(b0), "r"(b1));
}

__device__ __forceinline__ void ldsm4(
    uint32_t& r0, uint32_t& r1, uint32_t& r2, uint32_t& r3, uint32_t addr)
{
    asm volatile(
        "ldmatrix.sync.aligned.m8n8.x4.shared.b16 {%0,%1,%2,%3}, [%4];"
        : "=r"(r0), "=r"(r1), "=r"(r2), "=r"(r3) : "r"(addr));
}

__device__ __forceinline__ void ldsm4t(
    uint32_t& r0, uint32_t& r1, uint32_t& r2, uint32_t& r3, uint32_t addr)
{
    asm volatile(
        "ldmatrix.sync.aligned.m8n8.x4.trans.shared.b16 {%0,%1,%2,%3}, [%4];"
        : "=r"(r0), "=r"(r1), "=r"(r2), "=r"(r3) : "r"(addr));
}

__device__ __forceinline__ float ex2f(float x) {
    float r;
    asm("ex2.approx.f32 %0, %1;" : "=f"(r) : "f"(x));
    return r;
}

__device__ __forceinline__ uint32_t ex2_h2(float a, float b) {
    __half2 h = __floats2half2_rn(a, b);
    uint32_t r;
    asm("ex2.approx.f16x2 %0, %1;" : "=r"(r) : "r"(*(uint32_t*)&h));
    return r;
}

__device__ __forceinline__ void cp16(uint32_t smem_dst, const void* gsrc) {
    asm volatile("cp.async.cg.shared.global [%0], [%1], 16;\n"
                 :: "r"(smem_dst), "l"(gsrc));
}
__device__ __forceinline__ void cp_commit() {
    asm volatile("cp.async.commit_group;\n");
}
template<int N>
__device__ __forceinline__ void cp_wait() {
    asm volatile("cp.async.wait_group %0;\n" :: "n"(N));
}

// ---------------------------------------------------------------------------
// prologue conversions
// ---------------------------------------------------------------------------
__global__ __launch_bounds__(256) void cvt_h(
    const float* __restrict__ src, __half* __restrict__ dst, int n4)
{
    int i = blockIdx.x * blockDim.x + threadIdx.x;
    if (i < n4) {
        float4 v = ((const float4*)src)[i];
        __half2 h0 = __floats2half2_rn(v.x, v.y);
        __half2 h1 = __floats2half2_rn(v.z, v.w);
        *(uint2*)&dst[4 * i] = make_uint2(*(uint32_t*)&h0, *(uint32_t*)&h1);
    }
}

__global__ __launch_bounds__(256) void transcvt_w4(
    const float* __restrict__ W0, const float* __restrict__ W1,
    const float* __restrict__ W2, const float* __restrict__ W3,
    __half* __restrict__ T0, __half* __restrict__ T1,
    __half* __restrict__ T2, __half* __restrict__ T3)
{
    const int z = blockIdx.z;
    const float* W = (z == 0) ? W0 : (z == 1) ? W1 : (z == 2) ? W2 : W3;
    __half* Wt     = (z == 0) ? T0 : (z == 1) ? T1 : (z == 2) ? T2 : T3;

    __shared__ float t[32][33];
    const int n0 = blockIdx.x * 32;
    const int k0 = blockIdx.y * 32;
    const int tx = threadIdx.x;
    const int ty = threadIdx.y;
    #pragma unroll
    for (int i = 0; i < 32; i += 8)
        t[ty + i][tx] = W[(size_t)(k0 + ty + i) * EE + n0 + tx];
    __syncthreads();
    #pragma unroll
    for (int i = 0; i < 32; i += 8)
        Wt[(size_t)(n0 + ty + i) * EE + k0 + tx] = __float2half(t[tx][ty + i]);
}

// ---------------------------------------------------------------------------
// fp16 GEMM: CTA 128x128, 256 threads (8 warps 4x2), warp tile 32x64, BK=32,
// 3-stage cp.async, ldmatrix fragments. (unchanged from R14 winning version)
// ---------------------------------------------------------------------------
#define HAP 40
#define HSTG (128 * HAP)
#define HSMEM (3 * 2 * HSTG * 2)   // 61440 bytes

__device__ __forceinline__ void gemm16_body(
    const __half* __restrict__ A, const __half* __restrict__ Wt,
    const float* __restrict__ bias, void* Cv, int mode)
{
    extern __shared__ __half hsm[];
    __half* As = hsm;
    __half* Bs = hsm + 3 * HSTG;

    const int tid  = threadIdx.x;
    const int lane = tid & 31;
    const int warp = tid >> 5;
    const int gid  = lane >> 2;
    const int tig  = lane & 3;
    const int wm   = warp >> 1;
    const int wn   = warp & 1;
    const int m0   = blockIdx.y * 128;
    const int n0   = blockIdx.x * 128;

    const uint32_t a_base = (uint32_t)__cvta_generic_to_shared(As);
    const uint32_t b_base = (uint32_t)__cvta_generic_to_shared(Bs);

    const int srow = tid >> 1;
    const int scol = (tid & 1) * 16;

    const int arow_f = wm * 32 + (lane & 7) + ((lane >> 3) & 1) * 8;
    const int acol_f = ((lane >> 4) & 1) * 8;
    const int brow_f = wn * 64 + (lane & 7) + ((lane >> 4) & 1) * 8;
    const int bcol_f = ((lane >> 3) & 1) * 8;

    float acc[2][8][4] = {};
    const int nt = EE / 32;

    #pragma unroll
    for (int s = 0; s < 2; s++) {
        const __half* ag = &A [(size_t)(m0 + srow) * EE + s * 32 + scol];
        const __half* bg = &Wt[(size_t)(n0 + srow) * EE + s * 32 + scol];
        uint32_t ad = a_base + (s * HSTG + srow * HAP + scol) * 2;
        uint32_t bd = b_base + (s * HSTG + srow * HAP + scol) * 2;
        cp16(ad,      ag);   cp16(ad + 16, ag + 8);
        cp16(bd,      bg);   cp16(bd + 16, bg + 8);
        cp_commit();
    }

    for (int kt = 0; kt < nt; kt++) {
        cp_wait<1>();
        __syncthreads();

        if (kt + 2 < nt) {
            const int s = (kt + 2) % 3;
            const __half* ag = &A [(size_t)(m0 + srow) * EE + (kt + 2) * 32 + scol];
            const __half* bg = &Wt[(size_t)(n0 + srow) * EE + (kt + 2) * 32 + scol];
            uint32_t ad = a_base + (s * HSTG + srow * HAP + scol) * 2;
            uint32_t bd = b_base + (s * HSTG + srow * HAP + scol) * 2;
            cp16(ad,      ag);   cp16(ad + 16, ag + 8);
            cp16(bd,      bg);   cp16(bd + 16, bg + 8);
        }
        cp_commit();

        const uint32_t as_s = a_base + (kt % 3) * HSTG * 2;
        const uint32_t bs_s = b_base + (kt % 3) * HSTG * 2;

        #pragma unroll
        for (int ks = 0; ks < 2; ks++) {
            uint32_t af[2][4];
            #pragma unroll
            for (int i = 0; i < 2; i++)
                ldsm4(af[i][0], af[i][1], af[i][2], af[i][3],
                      as_s + (uint32_t)((arow_f + i * 16) * HAP + ks * 16 + acol_f) * 2);
            #pragma unroll
            for (int jp = 0; jp < 4; jp++) {
                uint32_t b00, b01, b10, b11;
                ldsm4(b00, b01, b10, b11,
                      bs_s + (uint32_t)((brow_f + jp * 16) * HAP + ks * 16 + bcol_f) * 2);
                #pragma unroll
                for (int i = 0; i < 2; i++) {
                    mma16(acc[i][2 * jp    ], af[i], b00, b01);
                    mma16(acc[i][2 * jp + 1], af[i], b10, b11);
                }
            }
        }
    }

    #pragma unroll
    for (int i = 0; i < 2; i++) {
        int r = m0 + wm * 32 + i * 16 + gid;
        #pragma unroll
        for (int j = 0; j < 8; j++) {
            int c = n0 + wn * 64 + j * 8 + 2 * tig;
            float2 bb = *(const float2*)&bias[c];
            float v00 = acc[i][j][0] + bb.x;
            float v01 = acc[i][j][1] + bb.y;
            float v10 = acc[i][j][2] + bb.x;
            float v11 = acc[i][j][3] + bb.y;
            if (mode == 0) {
                float* C = (float*)Cv;
                *(float2*)&C[(size_t)r * EE + c]       = make_float2(v00, v01);
                *(float2*)&C[(size_t)(r + 8) * EE + c] = make_float2(v10, v11);
            } else {
                if (mode == 2) { v00 *= QSCALE; v01 *= QSCALE; v10 *= QSCALE; v11 *= QSCALE; }
                __half* C = (__half*)Cv;
                *(__half2*)&C[(size_t)r * EE + c]       = __floats2half2_rn(v00, v01);
                *(__half2*)&C[(size_t)(r + 8) * EE + c] = __floats2half2_rn(v10, v11);
            }
        }
    }
}

__global__ __launch_bounds__(256, 2) void gemm16_qkv(
    const __half* __restrict__ x,
    const __half* __restrict__ Wq, const float* __restrict__ bq,
    const __half* __restrict__ Wk, const float* __restrict__ bk,
    const __half* __restrict__ Wv, const float* __restrict__ bv,
    __half* __restrict__ qp, __half* __restrict__ kp, __half* __restrict__ vp)
{
    const int z = blockIdx.z;
    const __half* W  = (z == 0) ? Wq : (z == 1) ? Wk : Wv;
    const float* bb  = (z == 0) ? bq : (z == 1) ? bk : bv;
    __half* C        = (z == 0) ? qp : (z == 1) ? kp : vp;
    gemm16_body(x, W, bb, C, (z == 0) ? 2 : 1);
}

__global__ __launch_bounds__(256, 2) void gemm16_out(
    const __half* __restrict__ A, const __half* __restrict__ Wt,
    const float* __restrict__ bias, float* __restrict__ C)
{
    gemm16_body(A, Wt, bias, C, 0);
}

// ---------------------------------------------------------------------------
// fp16 flash attention, causal (log2-domain). 256 threads = 8 warps.
// 4-stage cp.async K/V pipeline, ONE __syncthreads per tile:
// stage written at iter kt is (kt+2)%4 whose prior tile (kt-2) was finished
// by all warps before iter kt-1's barrier.
// smem: 4 stages x (K 64x72 + V 64x72) halves = 73728 B -> 2 CTA/SM.
// ---------------------------------------------------------------------------
#define KPH 72
#define STAGE_H (2 * 64 * KPH)
#define FSMEM (4 * STAGE_H * 2)           // 73728 bytes

__global__ __launch_bounds__(256, 2) void flash16(
    const __half* __restrict__ Qg, const __half* __restrict__ Kg,
    const __half* __restrict__ Vg, __half* __restrict__ ctx)
{
    extern __shared__ __half fsm[];

    const int tid  = threadIdx.x;
    const int lane = tid & 31;
    const int warp = tid >> 5;
    const int gid  = lane >> 2;
    const int tig  = lane & 3;
    const int qt2  = (int)gridDim.x - 1 - (int)blockIdx.x;  // heavy first
    const int h    = blockIdx.y;
    const int b    = blockIdx.z;
    const int q0   = qt2 * 128;
    const int wloc = (warp >> 2) * 64 + (warp & 3) * 16;
    const int wbase = q0 + wloc;
    const int nt   = 2 * qt2 + 2;

    const size_t base = (size_t)b * SS * EE + (size_t)h * DD;
    const uint32_t smem0 = (uint32_t)__cvta_generic_to_shared(fsm);

    const int srow = tid >> 2;
    const int scol = (tid & 3) * 16;
    const uint32_t soff = (uint32_t)(srow * KPH + scol) * 2;

    const int qrow_f = wloc + (lane & 7) + ((lane >> 3) & 1) * 8;
    const int qcol_f = ((lane >> 4) & 1) * 8;
    const int krow_f = (lane & 7) + ((lane >> 4) & 1) * 8;
    const int kcol_f = ((lane >> 3) & 1) * 8;
    const int vrow_t = (lane & 7) + ((lane >> 3) & 1) * 8;
    const int vcol_t = ((lane >> 4) & 1) * 8;

    // ---- stage Q (fp16, pre-scaled) into stage-0 region ----
    {
        const int qrow = tid >> 1;
        const int qh   = (tid & 1) * 32;
        const __half* qsrc = &Qg[base + (size_t)(q0 + qrow) * EE + qh];
        uint32_t qd = smem0 + (uint32_t)(qrow * KPH + qh) * 2;
        #pragma unroll
        for (int c = 0; c < 4; c++)
            cp16(qd + c * 16, qsrc + c * 8);
        cp_commit();
    }
    cp_wait<0>();
    __syncthreads();

    uint32_t qf[4][4];
    #pragma unroll
    for (int ks = 0; ks < 4; ks++)
        ldsm4(qf[ks][0], qf[ks][1], qf[ks][2], qf[ks][3],
              smem0 + (uint32_t)(qrow_f * KPH + ks * 16 + qcol_f) * 2);
    __syncthreads();   // all warps done reading Q before tile0 overwrites

    // prefetch tiles 0 and 1 (one commit group each)
    #pragma unroll
    for (int pt = 0; pt < 2; pt++) {
        if (pt < nt) {
            const uint32_t st = smem0 + (uint32_t)(pt * STAGE_H) * 2;
            const __half* kg = &Kg[base + (size_t)(pt * 64 + srow) * EE + scol];
            const __half* vg = &Vg[base + (size_t)(pt * 64 + srow) * EE + scol];
            cp16(st + soff,      kg);   cp16(st + soff + 16, kg + 8);
            cp16(st + (uint32_t)(64 * KPH) * 2 + soff,      vg);
            cp16(st + (uint32_t)(64 * KPH) * 2 + soff + 16, vg + 8);
        }
        cp_commit();
    }

    float oacc[8][4] = {};
    float m0r = -CUDART_INF_F, m1r = -CUDART_INF_F;
    float l0 = 0.f, l1 = 0.f;
    const int r0g = wbase + gid;
    const int r1g = r0g + 8;

    for (int kt = 0; kt < nt; kt++) {
        const int k0 = kt * 64;

        // prefetch tile kt+2 into stage (kt+2)%4 (safe: its prior tile kt-2
        // was finished by all warps before iter kt-1's barrier)
        if (kt + 2 < nt) {
            const int kn = (kt + 2) * 64;
            const uint32_t st = smem0 + (uint32_t)(((kt + 2) & 3) * STAGE_H) * 2;
            const __half* kg = &Kg[base + (size_t)(kn + srow) * EE + scol];
            const __half* vg = &Vg[base + (size_t)(kn + srow) * EE + scol];
            cp16(st + soff,      kg);   cp16(st + soff + 16, kg + 8);
            cp16(st + (uint32_t)(64 * KPH) * 2 + soff,      vg);
            cp16(st + (uint32_t)(64 * KPH) * 2 + soff + 16, vg + 8);
        }
        cp_commit();
        cp_wait<2>();      // tile kt has landed
        __syncthreads();   // single barrier: visibility + ordering

        if (k0 <= wbase + 15) {   // not fully masked for this warp
            const uint32_t KS_ = smem0 + (uint32_t)((kt & 3) * STAGE_H) * 2;
            const uint32_t VS_ = KS_ + (uint32_t)(64 * KPH) * 2;

            // S = Q @ K^T
            float sacc[8][4] = {};
            #pragma unroll
            for (int tp = 0; tp < 4; tp++) {
                #pragma unroll
                for (int ks = 0; ks < 4; ks++) {
                    uint32_t b00, b01, b10, b11;
                    ldsm4(b00, b01, b10, b11,
                          KS_ + (uint32_t)((krow_f + tp * 16) * KPH + ks * 16 + kcol_f) * 2);
                    mma16(sacc[2 * tp    ], qf[ks], b00, b01);
                    mma16(sacc[2 * tp + 1], qf[ks], b10, b11);
                }
            }

            // causal mask
            if (k0 + 63 > wbase) {
                #pragma unroll
                for (int t = 0; t < 8; t++) {
                    int c = k0 + t * 8 + 2 * tig;
                    if (c     > r0g) sacc[t][0] = -CUDART_INF_F;
                    if (c + 1 > r0g) sacc[t][1] = -CUDART_INF_F;
                    if (c     > r1g) sacc[t][2] = -CUDART_INF_F;
                    if (c + 1 > r1g) sacc[t][3] = -CUDART_INF_F;
                }
            }

            // online softmax (log2 domain)
            float vm0 = -CUDART_INF_F, vm1 = -CUDART_INF_F;
            #pragma unroll
            for (int t = 0; t < 8; t++) {
                vm0 = fmaxf(vm0, fmaxf(sacc[t][0], sacc[t][1]));
                vm1 = fmaxf(vm1, fmaxf(sacc[t][2], sacc[t][3]));
            }
            vm0 = fmaxf(vm0, __shfl_xor_sync(0xffffffffu, vm0, 1));
            vm0 = fmaxf(vm0, __shfl_xor_sync(0xffffffffu, vm0, 2));
            vm1 = fmaxf(vm1, __shfl_xor_sync(0xffffffffu, vm1, 1));
            vm1 = fmaxf(vm1, __shfl_xor_sync(0xffffffffu, vm1, 2));

            float mn0 = fmaxf(m0r, vm0), mn1 = fmaxf(m1r, vm1);
            float al0 = ex2f(m0r - mn0), al1 = ex2f(m1r - mn1);

            // P = 2^(s - mn) in fp16x2 — result IS the PV A-fragment
            uint32_t pf[4][4];
            float sum0 = 0.f, sum1 = 0.f;
            #pragma unroll
            for (int ks = 0; ks < 4; ks++) {
                #pragma unroll
                for (int u = 0; u < 2; u++) {
                    const float* s = sacc[2 * ks + u];
                    uint32_t e01 = ex2_h2(s[0] - mn0, s[1] - mn0);
                    uint32_t e23 = ex2_h2(s[2] - mn1, s[3] - mn1);
                    pf[ks][2 * u    ] = e01;
                    pf[ks][2 * u + 1] = e23;
                    float2 f01 = __half22float2(*(__half2*)&e01);
                    float2 f23 = __half22float2(*(__half2*)&e23);
                    sum0 += f01.x + f01.y;
                    sum1 += f23.x + f23.y;
                }
            }
            sum0 += __shfl_xor_sync(0xffffffffu, sum0, 1);
            sum0 += __shfl_xor_sync(0xffffffffu, sum0, 2);
            sum1 += __shfl_xor_sync(0xffffffffu, sum1, 1);
            sum1 += __shfl_xor_sync(0xffffffffu, sum1, 2);

            l0 = l0 * al0 + sum0;  m0r = mn0;
            l1 = l1 * al1 + sum1;  m1r = mn1;
            #pragma unroll
            for (int dt = 0; dt < 8; dt++) {
                oacc[dt][0] *= al0; oacc[dt][1] *= al0;
                oacc[dt][2] *= al1; oacc[dt][3] *= al1;
            }

            // O += P @ V (natural-layout V, ldmatrix.trans)
            #pragma unroll
            for (int ks = 0; ks < 4; ks++) {
                #pragma unroll
                for (int dp = 0; dp < 4; dp++) {
                    uint32_t b00, b01, b10, b11;
                    ldsm4t(b00, b01, b10, b11,
                           VS_ + (uint32_t)((ks * 16 + vrow_t) * KPH + dp * 16 + vcol_t) * 2);
                    mma16(oacc[2 * dp    ], pf[ks], b00, b01);
                    mma16(oacc[2 * dp + 1], pf[ks], b10, b11);
                }
            }
        }
    }

    // normalize + store ctx (fp16)
    float inv0 = 1.f / l0, inv1 = 1.f / l1;
    #pragma unroll
    for (int dt = 0; dt < 8; dt++) {
        int c = dt * 8 + 2 * tig;
        *(__half2*)&ctx[base + (size_t)r0g * EE + c] =
            __floats2half2_rn(oacc[dt][0] * inv0, oacc[dt][1] * inv0);
        *(__half2*)&ctx[base + (size_t)r1g * EE + c] =
            __floats2half2_rn(oacc[dt][2] * inv1, oacc[dt][3] * inv1);
    }
}

// ---------------------------------------------------------------------------
// Launch
// ---------------------------------------------------------------------------
extern "C" void kernel_launch(void* const* d_in, const int* in_sizes, int n_in,
                              void* d_out, int out_size)
{
    (void)in_sizes; (void)n_in; (void)out_size;
    const float* x  = (const float*)d_in[0];
    const float* Wq = (const float*)d_in[1];
    const float* bq = (const float*)d_in[2];
    const float* Wk = (const float*)d_in[3];
    const float* bk = (const float*)d_in[4];
    const float* Wv = (const float*)d_in[5];
    const float* bv = (const float*)d_in[6];
    const float* Wo = (const float*)d_in[7];
    const float* bo = (const float*)d_in[8];
    float* out = (float*)d_out;

    __half *qp, *kp, *vp, *cp, *xt, *wq, *wk, *wv, *wo;
    cudaGetSymbolAddress((void**)&qp,  g_q);
    cudaGetSymbolAddress((void**)&kp,  g_k);
    cudaGetSymbolAddress((void**)&vp,  g_v);
    cudaGetSymbolAddress((void**)&cp,  g_ctx);
    cudaGetSymbolAddress((void**)&xt,  g_xt);
    cudaGetSymbolAddress((void**)&wq,  g_wq);
    cudaGetSymbolAddress((void**)&wk,  g_wk);
    cudaGetSymbolAddress((void**)&wv,  g_wv);
    cudaGetSymbolAddress((void**)&wo,  g_wo);

    const int xn4 = BB * SS * EE / 4;
    cvt_h<<<xn4 / 256, 256>>>(x, xt, xn4);
    dim3 tb(32, 8);
    transcvt_w4<<<dim3(EE / 32, EE / 32, 4), tb>>>(Wq, Wk, Wv, Wo, wq, wk, wv, wo);

    cudaFuncSetAttribute(gemm16_qkv, cudaFuncAttributeMaxDynamicSharedMemorySize, HSMEM);
    cudaFuncSetAttribute(gemm16_out, cudaFuncAttributeMaxDynamicSharedMemorySize, HSMEM);
    cudaFuncSetAttribute(flash16, cudaFuncAttributeMaxDynamicSharedMemorySize, FSMEM);

    dim3 gqkv(EE / 128, (BB * SS) / 128, 3);   // (8, 32, 3)
    gemm16_qkv<<<gqkv, 256, HSMEM>>>(xt, wq, bq, wk, bk, wv, bv, qp, kp, vp);

    flash16<<<dim3(SS / 128, HH, BB), 256, FSMEM>>>(qp, kp, vp, cp);

    dim3 go(EE / 128, (BB * SS) / 128);        // (8, 32)
    gemm16_out<<<go, 256, HSMEM>>>(cp, wo, bo, out);
}

// round 16
// speedup vs baseline: 1.8412x; 1.0440x over previous
#include <cuda_runtime.h>
#include <cuda_fp16.h>
#include <math_constants.h>
#include <cstdint>

// Problem constants
#define BB 2
#define SS 2048
#define EE 1024
#define HH 16
#define DD 64

// Scratch (device globals — allocation-free rule)
__device__ __half g_q [BB * SS * EE];
__device__ __half g_k [BB * SS * EE];
__device__ __half g_v [BB * SS * EE];
__device__ __half g_ctx[BB * SS * EE];
__device__ __half g_xt[BB * SS * EE];        // x in fp16
__device__ __half g_wq[EE * EE];             // W^T in fp16: [N][K]
__device__ __half g_wk[EE * EE];
__device__ __half g_wv[EE * EE];
__device__ __half g_wo[EE * EE];

// Q pre-scale: (1/sqrt(64)) * log2(e)  -> scores in log2 units
#define QSCALE 0.1803368801111204f

// ---------------------------------------------------------------------------
// helpers
// ---------------------------------------------------------------------------
__device__ __forceinline__ void mma16(
    float* c, const uint32_t* a, uint32_t b0, uint32_t b1)
{
    asm volatile(
        "mma.sync.aligned.m16n8k16.row.col.f32.f16.f16.f32 "
        "{%0,%1,%2,%3},{%4,%5,%6,%7},{%8,%9},{%0,%1,%2,%3};\n"
        : "+f"(c[0]), "+f"(c[1]), "+f"(c[2]), "+f"(c[3])
        : "r"(a[0]), "r"(a[1]), "r"(a[2]), "r"(a[3]), "r"(b0), "r"(b1));
}

__device__ __forceinline__ void ldsm4(
    uint32_t& r0, uint32_t& r1, uint32_t& r2, uint32_t& r3, uint32_t addr)
{
    asm volatile(
        "ldmatrix.sync.aligned.m8n8.x4.shared.b16 {%0,%1,%2,%3}, [%4];"
        : "=r"(r0), "=r"(r1), "=r"(r2), "=r"(r3) : "r"(addr));
}

__device__ __forceinline__ void ldsm4t(
    uint32_t& r0, uint32_t& r1, uint32_t& r2, uint32_t& r3, uint32_t addr)
{
    asm volatile(
        "ldmatrix.sync.aligned.m8n8.x4.trans.shared.b16 {%0,%1,%2,%3}, [%4];"
        : "=r"(r0), "=r"(r1), "=r"(r2), "=r"(r3) : "r"(addr));
}

__device__ __forceinline__ float ex2f(float x) {
    float r;
    asm("ex2.approx.f32 %0, %1;" : "=f"(r) : "f"(x));
    return r;
}

__device__ __forceinline__ uint32_t ex2_h2(float a, float b) {
    __half2 h = __floats2half2_rn(a, b);
    uint32_t r;
    asm("ex2.approx.f16x2 %0, %1;" : "=r"(r) : "r"(*(uint32_t*)&h));
    return r;
}

__device__ __forceinline__ void cp16(uint32_t smem_dst, const void* gsrc) {
    asm volatile("cp.async.cg.shared.global [%0], [%1], 16;\n"
                 :: "r"(smem_dst), "l"(gsrc));
}
__device__ __forceinline__ void cp_commit() {
    asm volatile("cp.async.commit_group;\n");
}
template<int N>
__device__ __forceinline__ void cp_wait() {
    asm volatile("cp.async.wait_group %0;\n" :: "n"(N));
}

// ---------------------------------------------------------------------------
// fused prologue: z<4 -> transpose+cvt W[z]; z==4 -> cvt x (grid-stride)
// ---------------------------------------------------------------------------
__global__ __launch_bounds__(256) void prep_all(
    const float* __restrict__ x, __half* __restrict__ xt,
    const float* __restrict__ W0, const float* __restrict__ W1,
    const float* __restrict__ W2, const float* __restrict__ W3,
    __half* __restrict__ T0, __half* __restrict__ T1,
    __half* __restrict__ T2, __half* __restrict__ T3)
{
    const int z = blockIdx.z;
    if (z < 4) {
        const float* W = (z == 0) ? W0 : (z == 1) ? W1 : (z == 2) ? W2 : W3;
        __half* Wt     = (z == 0) ? T0 : (z == 1) ? T1 : (z == 2) ? T2 : T3;
        __shared__ float t[32][33];
        const int n0 = blockIdx.x * 32;
        const int k0 = blockIdx.y * 32;
        const int tx = threadIdx.x;
        const int ty = threadIdx.y;
        #pragma unroll
        for (int i = 0; i < 32; i += 8)
            t[ty + i][tx] = W[(size_t)(k0 + ty + i) * EE + n0 + tx];
        __syncthreads();
        #pragma unroll
        for (int i = 0; i < 32; i += 8)
            Wt[(size_t)(n0 + ty + i) * EE + k0 + tx] = __float2half(t[tx][ty + i]);
    } else {
        const int n4 = BB * SS * EE / 4;                 // 1048576
        const int nthreads = gridDim.x * gridDim.y * 256; // 262144
        int g = (blockIdx.y * gridDim.x + blockIdx.x) * 256
              + threadIdx.y * 32 + threadIdx.x;
        for (int i = g; i < n4; i += nthreads) {
            float4 v = ((const float4*)x)[i];
            __half2 h0 = __floats2half2_rn(v.x, v.y);
            __half2 h1 = __floats2half2_rn(v.z, v.w);
            *(uint2*)&xt[4 * i] = make_uint2(*(uint32_t*)&h0, *(uint32_t*)&h1);
        }
    }
}

// ---------------------------------------------------------------------------
// fp16 GEMM: CTA 128x128, 256 threads (8 warps 4x2), warp tile 32x64, BK=32,
// 3-stage cp.async, ldmatrix fragments. (unchanged from R14/R15 winner)
// ---------------------------------------------------------------------------
#define HAP 40
#define HSTG (128 * HAP)
#define HSMEM (3 * 2 * HSTG * 2)   // 61440 bytes

__device__ __forceinline__ void gemm16_body(
    const __half* __restrict__ A, const __half* __restrict__ Wt,
    const float* __restrict__ bias, void* Cv, int mode)
{
    extern __shared__ __half hsm[];
    __half* As = hsm;
    __half* Bs = hsm + 3 * HSTG;

    const int tid  = threadIdx.x;
    const int lane = tid & 31;
    const int warp = tid >> 5;
    const int gid  = lane >> 2;
    const int tig  = lane & 3;
    const int wm   = warp >> 1;
    const int wn   = warp & 1;
    const int m0   = blockIdx.y * 128;
    const int n0   = blockIdx.x * 128;

    const uint32_t a_base = (uint32_t)__cvta_generic_to_shared(As);
    const uint32_t b_base = (uint32_t)__cvta_generic_to_shared(Bs);

    const int srow = tid >> 1;
    const int scol = (tid & 1) * 16;

    const int arow_f = wm * 32 + (lane & 7) + ((lane >> 3) & 1) * 8;
    const int acol_f = ((lane >> 4) & 1) * 8;
    const int brow_f = wn * 64 + (lane & 7) + ((lane >> 4) & 1) * 8;
    const int bcol_f = ((lane >> 3) & 1) * 8;

    float acc[2][8][4] = {};
    const int nt = EE / 32;

    #pragma unroll
    for (int s = 0; s < 2; s++) {
        const __half* ag = &A [(size_t)(m0 + srow) * EE + s * 32 + scol];
        const __half* bg = &Wt[(size_t)(n0 + srow) * EE + s * 32 + scol];
        uint32_t ad = a_base + (s * HSTG + srow * HAP + scol) * 2;
        uint32_t bd = b_base + (s * HSTG + srow * HAP + scol) * 2;
        cp16(ad,      ag);   cp16(ad + 16, ag + 8);
        cp16(bd,      bg);   cp16(bd + 16, bg + 8);
        cp_commit();
    }

    for (int kt = 0; kt < nt; kt++) {
        cp_wait<1>();
        __syncthreads();

        if (kt + 2 < nt) {
            const int s = (kt + 2) % 3;
            const __half* ag = &A [(size_t)(m0 + srow) * EE + (kt + 2) * 32 + scol];
            const __half* bg = &Wt[(size_t)(n0 + srow) * EE + (kt + 2) * 32 + scol];
            uint32_t ad = a_base + (s * HSTG + srow * HAP + scol) * 2;
            uint32_t bd = b_base + (s * HSTG + srow * HAP + scol) * 2;
            cp16(ad,      ag);   cp16(ad + 16, ag + 8);
            cp16(bd,      bg);   cp16(bd + 16, bg + 8);
        }
        cp_commit();

        const uint32_t as_s = a_base + (kt % 3) * HSTG * 2;
        const uint32_t bs_s = b_base + (kt % 3) * HSTG * 2;

        #pragma unroll
        for (int ks = 0; ks < 2; ks++) {
            uint32_t af[2][4];
            #pragma unroll
            for (int i = 0; i < 2; i++)
                ldsm4(af[i][0], af[i][1], af[i][2], af[i][3],
                      as_s + (uint32_t)((arow_f + i * 16) * HAP + ks * 16 + acol_f) * 2);
            #pragma unroll
            for (int jp = 0; jp < 4; jp++) {
                uint32_t b00, b01, b10, b11;
                ldsm4(b00, b01, b10, b11,
                      bs_s + (uint32_t)((brow_f + jp * 16) * HAP + ks * 16 + bcol_f) * 2);
                #pragma unroll
                for (int i = 0; i < 2; i++) {
                    mma16(acc[i][2 * jp    ], af[i], b00, b01);
                    mma16(acc[i][2 * jp + 1], af[i], b10, b11);
                }
            }
        }
    }

    #pragma unroll
    for (int i = 0; i < 2; i++) {
        int r = m0 + wm * 32 + i * 16 + gid;
        #pragma unroll
        for (int j = 0; j < 8; j++) {
            int c = n0 + wn * 64 + j * 8 + 2 * tig;
            float2 bb = *(const float2*)&bias[c];
            float v00 = acc[i][j][0] + bb.x;
            float v01 = acc[i][j][1] + bb.y;
            float v10 = acc[i][j][2] + bb.x;
            float v11 = acc[i][j][3] + bb.y;
            if (mode == 0) {
                float* C = (float*)Cv;
                *(float2*)&C[(size_t)r * EE + c]       = make_float2(v00, v01);
                *(float2*)&C[(size_t)(r + 8) * EE + c] = make_float2(v10, v11);
            } else {
                if (mode == 2) { v00 *= QSCALE; v01 *= QSCALE; v10 *= QSCALE; v11 *= QSCALE; }
                __half* C = (__half*)Cv;
                *(__half2*)&C[(size_t)r * EE + c]       = __floats2half2_rn(v00, v01);
                *(__half2*)&C[(size_t)(r + 8) * EE + c] = __floats2half2_rn(v10, v11);
            }
        }
    }
}

__global__ __launch_bounds__(256, 2) void gemm16_qkv(
    const __half* __restrict__ x,
    const __half* __restrict__ Wq, const float* __restrict__ bq,
    const __half* __restrict__ Wk, const float* __restrict__ bk,
    const __half* __restrict__ Wv, const float* __restrict__ bv,
    __half* __restrict__ qp, __half* __restrict__ kp, __half* __restrict__ vp)
{
    const int z = blockIdx.z;
    const __half* W  = (z == 0) ? Wq : (z == 1) ? Wk : Wv;
    const float* bb  = (z == 0) ? bq : (z == 1) ? bk : bv;
    __half* C        = (z == 0) ? qp : (z == 1) ? kp : vp;
    gemm16_body(x, W, bb, C, (z == 0) ? 2 : 1);
}

__global__ __launch_bounds__(256, 2) void gemm16_out(
    const __half* __restrict__ A, const __half* __restrict__ Wt,
    const float* __restrict__ bias, float* __restrict__ C)
{
    gemm16_body(A, Wt, bias, C, 0);
}

// ---------------------------------------------------------------------------
// fp16 flash attention, causal (log2-domain). 256 threads = 8 warps.
// 4-stage cp.async pipeline, one barrier/tile. Row sums via ones-mma
// (P @ 1) on the tensor pipe — no shuffles/converts in the scalar path.
// ---------------------------------------------------------------------------
#define KPH 72
#define STAGE_H (2 * 64 * KPH)
#define FSMEM (4 * STAGE_H * 2)           // 73728 bytes

__global__ __launch_bounds__(256, 2) void flash16(
    const __half* __restrict__ Qg, const __half* __restrict__ Kg,
    const __half* __restrict__ Vg, __half* __restrict__ ctx)
{
    extern __shared__ __half fsm[];

    const int tid  = threadIdx.x;
    const int lane = tid & 31;
    const int warp = tid >> 5;
    const int gid  = lane >> 2;
    const int tig  = lane & 3;
    const int qt2  = (int)gridDim.x - 1 - (int)blockIdx.x;  // heavy first
    const int h    = blockIdx.y;
    const int b    = blockIdx.z;
    const int q0   = qt2 * 128;
    const int wloc = (warp >> 2) * 64 + (warp & 3) * 16;
    const int wbase = q0 + wloc;
    const int nt   = 2 * qt2 + 2;

    const size_t base = (size_t)b * SS * EE + (size_t)h * DD;
    const uint32_t smem0 = (uint32_t)__cvta_generic_to_shared(fsm);

    const int srow = tid >> 2;
    const int scol = (tid & 3) * 16;
    const uint32_t soff = (uint32_t)(srow * KPH + scol) * 2;

    const int qrow_f = wloc + (lane & 7) + ((lane >> 3) & 1) * 8;
    const int qcol_f = ((lane >> 4) & 1) * 8;
    const int krow_f = (lane & 7) + ((lane >> 4) & 1) * 8;
    const int kcol_f = ((lane >> 3) & 1) * 8;
    const int vrow_t = (lane & 7) + ((lane >> 3) & 1) * 8;
    const int vcol_t = ((lane >> 4) & 1) * 8;

    // ---- stage Q (fp16, pre-scaled) ----
    {
        const int qrow = tid >> 1;
        const int qh   = (tid & 1) * 32;
        const __half* qsrc = &Qg[base + (size_t)(q0 + qrow) * EE + qh];
        uint32_t qd = smem0 + (uint32_t)(qrow * KPH + qh) * 2;
        #pragma unroll
        for (int c = 0; c < 4; c++)
            cp16(qd + c * 16, qsrc + c * 8);
        cp_commit();
    }
    cp_wait<0>();
    __syncthreads();

    uint32_t qf[4][4];
    #pragma unroll
    for (int ks = 0; ks < 4; ks++)
        ldsm4(qf[ks][0], qf[ks][1], qf[ks][2], qf[ks][3],
              smem0 + (uint32_t)(qrow_f * KPH + ks * 16 + qcol_f) * 2);
    __syncthreads();

    // prefetch tiles 0, 1
    #pragma unroll
    for (int pt = 0; pt < 2; pt++) {
        if (pt < nt) {
            const uint32_t st = smem0 + (uint32_t)(pt * STAGE_H) * 2;
            const __half* kg = &Kg[base + (size_t)(pt * 64 + srow) * EE + scol];
            const __half* vg = &Vg[base + (size_t)(pt * 64 + srow) * EE + scol];
            cp16(st + soff,      kg);   cp16(st + soff + 16, kg + 8);
            cp16(st + (uint32_t)(64 * KPH) * 2 + soff,      vg);
            cp16(st + (uint32_t)(64 * KPH) * 2 + soff + 16, vg + 8);
        }
        cp_commit();
    }

    float oacc[8][4] = {};
    float m0r = -CUDART_INF_F, m1r = -CUDART_INF_F;
    float l0 = 0.f, l1 = 0.f;
    const int r0g = wbase + gid;
    const int r1g = r0g + 8;
    const uint32_t ONE2 = 0x3C003C00u;   // half2(1.0, 1.0)

    for (int kt = 0; kt < nt; kt++) {
        const int k0 = kt * 64;

        if (kt + 2 < nt) {
            const int kn = (kt + 2) * 64;
            const uint32_t st = smem0 + (uint32_t)(((kt + 2) & 3) * STAGE_H) * 2;
            const __half* kg = &Kg[base + (size_t)(kn + srow) * EE + scol];
            const __half* vg = &Vg[base + (size_t)(kn + srow) * EE + scol];
            cp16(st + soff,      kg);   cp16(st + soff + 16, kg + 8);
            cp16(st + (uint32_t)(64 * KPH) * 2 + soff,      vg);
            cp16(st + (uint32_t)(64 * KPH) * 2 + soff + 16, vg + 8);
        }
        cp_commit();
        cp_wait<2>();
        __syncthreads();

        if (k0 <= wbase + 15) {
            const uint32_t KS_ = smem0 + (uint32_t)((kt & 3) * STAGE_H) * 2;
            const uint32_t VS_ = KS_ + (uint32_t)(64 * KPH) * 2;

            // S = Q @ K^T
            float sacc[8][4] = {};
            #pragma unroll
            for (int tp = 0; tp < 4; tp++) {
                #pragma unroll
                for (int ks = 0; ks < 4; ks++) {
                    uint32_t b00, b01, b10, b11;
                    ldsm4(b00, b01, b10, b11,
                          KS_ + (uint32_t)((krow_f + tp * 16) * KPH + ks * 16 + kcol_f) * 2);
                    mma16(sacc[2 * tp    ], qf[ks], b00, b01);
                    mma16(sacc[2 * tp + 1], qf[ks], b10, b11);
                }
            }

            // causal mask
            if (k0 + 63 > wbase) {
                #pragma unroll
                for (int t = 0; t < 8; t++) {
                    int c = k0 + t * 8 + 2 * tig;
                    if (c     > r0g) sacc[t][0] = -CUDART_INF_F;
                    if (c + 1 > r0g) sacc[t][1] = -CUDART_INF_F;
                    if (c     > r1g) sacc[t][2] = -CUDART_INF_F;
                    if (c + 1 > r1g) sacc[t][3] = -CUDART_INF_F;
                }
            }

            // online max (shuffle) — sums are done on the tensor pipe below
            float vm0 = -CUDART_INF_F, vm1 = -CUDART_INF_F;
            #pragma unroll
            for (int t = 0; t < 8; t++) {
                vm0 = fmaxf(vm0, fmaxf(sacc[t][0], sacc[t][1]));
                vm1 = fmaxf(vm1, fmaxf(sacc[t][2], sacc[t][3]));
            }
            vm0 = fmaxf(vm0, __shfl_xor_sync(0xffffffffu, vm0, 1));
            vm0 = fmaxf(vm0, __shfl_xor_sync(0xffffffffu, vm0, 2));
            vm1 = fmaxf(vm1, __shfl_xor_sync(0xffffffffu, vm1, 1));
            vm1 = fmaxf(vm1, __shfl_xor_sync(0xffffffffu, vm1, 2));

            float mn0 = fmaxf(m0r, vm0), mn1 = fmaxf(m1r, vm1);
            float al0 = ex2f(m0r - mn0), al1 = ex2f(m1r - mn1);

            // P = 2^(s - mn) in fp16x2 — result IS the PV A-fragment
            uint32_t pf[4][4];
            #pragma unroll
            for (int ks = 0; ks < 4; ks++) {
                #pragma unroll
                for (int u = 0; u < 2; u++) {
                    const float* s = sacc[2 * ks + u];
                    pf[ks][2 * u    ] = ex2_h2(s[0] - mn0, s[1] - mn0);
                    pf[ks][2 * u + 1] = ex2_h2(s[2] - mn1, s[3] - mn1);
                }
            }

            // row sums on the tensor pipe: lacc = P @ 1
            float lacc[4] = {0.f, 0.f, 0.f, 0.f};
            #pragma unroll
            for (int ks = 0; ks < 4; ks++)
                mma16(lacc, pf[ks], ONE2, ONE2);

            l0 = l0 * al0 + lacc[0];  m0r = mn0;
            l1 = l1 * al1 + lacc[2];  m1r = mn1;
            #pragma unroll
            for (int dt = 0; dt < 8; dt++) {
                oacc[dt][0] *= al0; oacc[dt][1] *= al0;
                oacc[dt][2] *= al1; oacc[dt][3] *= al1;
            }

            // O += P @ V (natural-layout V, ldmatrix.trans)
            #pragma unroll
            for (int ks = 0; ks < 4; ks++) {
                #pragma unroll
                for (int dp = 0; dp < 4; dp++) {
                    uint32_t b00, b01, b10, b11;
                    ldsm4t(b00, b01, b10, b11,
                           VS_ + (uint32_t)((ks * 16 + vrow_t) * KPH + dp * 16 + vcol_t) * 2);
                    mma16(oacc[2 * dp    ], pf[ks], b00, b01);
                    mma16(oacc[2 * dp + 1], pf[ks], b10, b11);
                }
            }
        }
    }

    // normalize + store ctx (fp16)
    float inv0 = 1.f / l0, inv1 = 1.f / l1;
    #pragma unroll
    for (int dt = 0; dt < 8; dt++) {
        int c = dt * 8 + 2 * tig;
        *(__half2*)&ctx[base + (size_t)r0g * EE + c] =
            __floats2half2_rn(oacc[dt][0] * inv0, oacc[dt][1] * inv0);
        *(__half2*)&ctx[base + (size_t)r1g * EE + c] =
            __floats2half2_rn(oacc[dt][2] * inv1, oacc[dt][3] * inv1);
    }
}

// ---------------------------------------------------------------------------
// Launch
// ---------------------------------------------------------------------------
extern "C" void kernel_launch(void* const* d_in, const int* in_sizes, int n_in,
                              void* d_out, int out_size)
{
    (void)in_sizes; (void)n_in; (void)out_size;
    const float* x  = (const float*)d_in[0];
    const float* Wq = (const float*)d_in[1];
    const float* bq = (const float*)d_in[2];
    const float* Wk = (const float*)d_in[3];
    const float* bk = (const float*)d_in[4];
    const float* Wv = (const float*)d_in[5];
    const float* bv = (const float*)d_in[6];
    const float* Wo = (const float*)d_in[7];
    const float* bo = (const float*)d_in[8];
    float* out = (float*)d_out;

    __half *qp, *kp, *vp, *cp, *xt, *wq, *wk, *wv, *wo;
    cudaGetSymbolAddress((void**)&qp,  g_q);
    cudaGetSymbolAddress((void**)&kp,  g_k);
    cudaGetSymbolAddress((void**)&vp,  g_v);
    cudaGetSymbolAddress((void**)&cp,  g_ctx);
    cudaGetSymbolAddress((void**)&xt,  g_xt);
    cudaGetSymbolAddress((void**)&wq,  g_wq);
    cudaGetSymbolAddress((void**)&wk,  g_wk);
    cudaGetSymbolAddress((void**)&wv,  g_wv);
    cudaGetSymbolAddress((void**)&wo,  g_wo);

    dim3 tb(32, 8);
    prep_all<<<dim3(EE / 32, EE / 32, 5), tb>>>(
        x, xt, Wq, Wk, Wv, Wo, wq, wk, wv, wo);

    cudaFuncSetAttribute(gemm16_qkv, cudaFuncAttributeMaxDynamicSharedMemorySize, HSMEM);
    cudaFuncSetAttribute(gemm16_out, cudaFuncAttributeMaxDynamicSharedMemorySize, HSMEM);
    cudaFuncSetAttribute(flash16, cudaFuncAttributeMaxDynamicSharedMemorySize, FSMEM);

    dim3 gqkv(EE / 128, (BB * SS) / 128, 3);   // (8, 32, 3)
    gemm16_qkv<<<gqkv, 256, HSMEM>>>(xt, wq, bq, wk, bk, wv, bv, qp, kp, vp);

    flash16<<<dim3(SS / 128, HH, BB), 256, FSMEM>>>(qp, kp, vp, cp);

    dim3 go(EE / 128, (BB * SS) / 128);        // (8, 32)
    gemm16_out<<<go, 256, HSMEM>>>(cp, wo, bo, out);
}